// round 11
// baseline (speedup 1.0000x reference)
#include <cuda_runtime.h>
#include <cstdint>

// Problem constants (fixed by the reference: SHAPE = (8192, 4096), P = 0.3)
#define N_ELEMS   (8192 * 4096)        // 33,554,432 floats
#define N_WORDS   (N_ELEMS / 32)       // 1,048,576 uint32 mask words = 4 MB
#define N_FLOAT4  (N_ELEMS / 4)        // 8,388,608 float4s

// Scratch: 1 bit per element. Zero at module load; apply re-zeroes it every
// pass for the next graph replay (self-cleaning).
__device__ uint32_t g_mask[N_WORDS];

// ---------------------------------------------------------------------------
// Kernel 1: scatter-set bits from the int32 index list.
// Flat launch, 512-thread blocks, 8 indices per thread via TWO front-batched
// int4 loads (MLP=2 on the idx stream), then 8 fire-and-forget RED.ORs.
// The kernel is L1tex-wavefront bound at ~1.3 cyc per scattered RED lane;
// this shape minimizes per-thread latency exposure and block count.
// ---------------------------------------------------------------------------
__global__ void __launch_bounds__(512)
set_bits_kernel(const int4* __restrict__ idx4, int n_octs, int k) {
    int i = blockIdx.x * blockDim.x + threadIdx.x;
    if (i < n_octs) {
        int4 v0 = idx4[2 * i];
        int4 v1 = idx4[2 * i + 1];
        unsigned int a0 = (unsigned int)v0.x, a1 = (unsigned int)v0.y;
        unsigned int a2 = (unsigned int)v0.z, a3 = (unsigned int)v0.w;
        unsigned int a4 = (unsigned int)v1.x, a5 = (unsigned int)v1.y;
        unsigned int a6 = (unsigned int)v1.z, a7 = (unsigned int)v1.w;
        atomicOr(&g_mask[a0 >> 5], 1u << (a0 & 31));
        atomicOr(&g_mask[a1 >> 5], 1u << (a1 & 31));
        atomicOr(&g_mask[a2 >> 5], 1u << (a2 & 31));
        atomicOr(&g_mask[a3 >> 5], 1u << (a3 & 31));
        atomicOr(&g_mask[a4 >> 5], 1u << (a4 & 31));
        atomicOr(&g_mask[a5 >> 5], 1u << (a5 & 31));
        atomicOr(&g_mask[a6 >> 5], 1u << (a6 & 31));
        atomicOr(&g_mask[a7 >> 5], 1u << (a7 & 31));
    }
    // tail (k % 8 != 0): handled scalar by thread 0
    if (i == 0) {
        const int* idx = (const int*)idx4;
        for (int j = n_octs * 8; j < k; j++) {
            unsigned int a = (unsigned int)idx[j];
            atomicOr(&g_mask[a >> 5], 1u << (a & 31));
        }
    }
}

// ---------------------------------------------------------------------------
// Kernel 2: fused copy + masked zero + mask self-clean.
// Best-measured config (R4, 38.1us): 256 threads, ILP=4 block-strided,
// block covers 1024 consecutive float4s. Coalesced: consecutive threads ->
// consecutive float4s (4 wavefronts per LDG.128). 8 adjacent same-warp
// threads share one mask word; the (tid&7)==0 lane cleans its group's four
// words AFTER the loads — readers and cleaner share a warp, so warp program
// order makes the self-clean race-free. X read .cs, out written .cs.
// ---------------------------------------------------------------------------
__global__ void __launch_bounds__(256)
apply_mask_kernel(const float4* __restrict__ X, float4* __restrict__ out) {
    int tid = threadIdx.x;
    int base = blockIdx.x * 1024 + tid;

    int i0 = base;
    int i1 = base + 256;
    int i2 = base + 512;
    int i3 = base + 768;

    uint32_t w0 = g_mask[i0 >> 3];
    uint32_t w1 = g_mask[i1 >> 3];
    uint32_t w2 = g_mask[i2 >> 3];
    uint32_t w3 = g_mask[i3 >> 3];
    float4 v0 = __ldcs(&X[i0]);
    float4 v1 = __ldcs(&X[i1]);
    float4 v2 = __ldcs(&X[i2]);
    float4 v3 = __ldcs(&X[i3]);

    uint32_t n0 = w0 >> ((i0 & 7) * 4);
    if (n0 & 1u) v0.x = 0.0f;
    if (n0 & 2u) v0.y = 0.0f;
    if (n0 & 4u) v0.z = 0.0f;
    if (n0 & 8u) v0.w = 0.0f;
    __stcs(&out[i0], v0);

    uint32_t n1 = w1 >> ((i1 & 7) * 4);
    if (n1 & 1u) v1.x = 0.0f;
    if (n1 & 2u) v1.y = 0.0f;
    if (n1 & 4u) v1.z = 0.0f;
    if (n1 & 8u) v1.w = 0.0f;
    __stcs(&out[i1], v1);

    uint32_t n2 = w2 >> ((i2 & 7) * 4);
    if (n2 & 1u) v2.x = 0.0f;
    if (n2 & 2u) v2.y = 0.0f;
    if (n2 & 4u) v2.z = 0.0f;
    if (n2 & 8u) v2.w = 0.0f;
    __stcs(&out[i2], v2);

    uint32_t n3 = w3 >> ((i3 & 7) * 4);
    if (n3 & 1u) v3.x = 0.0f;
    if (n3 & 2u) v3.y = 0.0f;
    if (n3 & 4u) v3.z = 0.0f;
    if (n3 & 8u) v3.w = 0.0f;
    __stcs(&out[i3], v3);

    // self-clean for next graph replay (one lane per 8-thread group cleans
    // that group's four mask words; same warp as all readers of those words)
    if ((tid & 7) == 0) {
        g_mask[i0 >> 3] = 0u;
        g_mask[i1 >> 3] = 0u;
        g_mask[i2 >> 3] = 0u;
        g_mask[i3 >> 3] = 0u;
    }
}

extern "C" void kernel_launch(void* const* d_in, const int* in_sizes, int n_in,
                              void* d_out, int out_size) {
    const float* X = (const float*)d_in[0];
    const int* drop_idx = (const int*)d_in[1];   // JAX x64-disabled => int32
    int k = in_sizes[1];                          // number of indices
    float* out = (float*)d_out;

    // 1) scatter bits (mask is zero: module init or previous apply)
    {
        int n_octs = k / 8;
        int threads = 512;
        int blocks = (n_octs + threads - 1) / threads;   // flat
        set_bits_kernel<<<blocks, threads>>>((const int4*)drop_idx, n_octs, k);
    }

    // 2) fused copy + zero + mask clear (1024 float4s per 256-thread block)
    {
        int blocks = N_FLOAT4 / 1024;   // 8192
        apply_mask_kernel<<<blocks, 256>>>((const float4*)X, (float4*)out);
    }
}